// round 2
// baseline (speedup 1.0000x reference)
#include <cuda_runtime.h>
#include <cstdint>

// features: [B=16, H=128, W=128, D=8, F=16] float32, row-major.
// out[b,h,w,d,f] = valid(i,j) ? in[b, si(i,j), sj(i,j), 7-d, f] : 0
//   i = (h-5) mod 128, j = (134-w) mod 128
//   (si,sj) = round_ne( Rinv * (i-63.5, j-63.5) + 63.5 ), Rinv for +40 deg.
//
// One thread = one float4 (16B). 32 float4 per (b,h,w) chunk of 512B.
// Both src and dst accesses are fully coalesced (d-flip permutes 16B granules
// inside the same 512B chunk).

__global__ __launch_bounds__(256) void Augment_70566312673947_kernel(
    const float4* __restrict__ in, float4* __restrict__ out)
{
    // cos(40deg), sin(40deg) rounded to float32
    const float c = 0.76604443f;   // 0.766044443118978
    const float s = 0.64278761f;   // 0.642787609686539

    int gid = blockIdx.x * blockDim.x + threadIdx.x;   // 0 .. 8388607
    int lane  = gid & 31;          // float4 index within 512B chunk
    int chunk = gid >> 5;          // b*H*W + h*W + w   (0 .. 262143)

    int w = chunk & 127;
    int h = (chunk >> 7) & 127;
    int b = chunk >> 14;

    // roll^-1 then flip-W composed
    int i = h - 5; if (i < 0) i += 128;
    int j = (134 - w) & 127;

    // inverse rotation, float32 ops kept un-fused to match XLA f32 math
    float fi = (float)i - 63.5f;
    float fj = (float)j - 63.5f;
    float src_i = __fadd_rn(__fadd_rn(__fmul_rn(c, fi), __fmul_rn(s, fj)), 63.5f);
    float src_j = __fadd_rn(__fadd_rn(__fmul_rn(-s, fi), __fmul_rn(c, fj)), 63.5f);
    int si = __float2int_rn(src_i);   // round-half-to-even == jnp.round
    int sj = __float2int_rn(src_j);

    float4 v = make_float4(0.f, 0.f, 0.f, 0.f);
    if (si >= 0 && si < 128 && sj >= 0 && sj < 128) {
        // flip D: out granule lane=(d*4 + f4) reads src granule ((7-d)*4 + f4)
        int d  = lane >> 2;
        int f4 = lane & 3;
        int srclane = ((7 - d) << 2) | f4;
        size_t src_chunk = (((size_t)b * 128 + si) * 128 + sj);
        v = in[src_chunk * 32 + srclane];
    }
    out[gid] = v;
}

extern "C" void kernel_launch(void* const* d_in, const int* in_sizes, int n_in,
                              void* d_out, int out_size)
{
    const float4* in  = (const float4*)d_in[0];
    float4*       out = (float4*)d_out;
    // total float4s = 16*128*128*8*16 / 4 = 8,388,608
    int total = out_size / 4;
    int threads = 256;
    int blocks = (total + threads - 1) / threads;   // 32768
    Augment_70566312673947_kernel<<<blocks, threads>>>(in, out);
}

// round 3
// speedup vs baseline: 1.0452x; 1.0452x over previous
#include <cuda_runtime.h>
#include <cstdint>

// features: [B=16, H=128, W=128, D=8, F=16] float32, row-major.
// out[b,h,w,d,f] = valid(i,j) ? in[b, si(i,j), sj(i,j), 7-d, f] : 0
//   i = (h-5) mod 128, j = (134-w) mod 128
//   (si,sj) = round_ne( Rinv * (i-63.5, j-63.5) + 63.5 ), Rinv for +40 deg.
//
// One thread = one float4 lane within a 512B (d,f) chunk, for FOUR batches
// (b, b+4, b+8, b+12). Rotation math computed once per thread; 4 independent
// loads give MLP=4. Streaming stores keep input resident in L2.

#define ILP 4

__global__ __launch_bounds__(256) void Augment_70566312673947_kernel(
    const float4* __restrict__ in, float4* __restrict__ out)
{
    const float c = 0.76604443f;   // cos(40deg) rounded to f32
    const float s = 0.64278761f;   // sin(40deg) rounded to f32

    int tid = blockIdx.x * blockDim.x + threadIdx.x;   // 0 .. 2,097,151
    int lane  = tid & 31;          // float4 index within 512B chunk
    int chunk = tid >> 5;          // b0*H*W + h*W + w, b0 in [0,4)

    int w = chunk & 127;
    int h = (chunk >> 7) & 127;

    // roll^-1 then flip-W composed
    int i = h - 5; if (i < 0) i += 128;
    int j = (134 - w) & 127;

    // inverse rotation (f32 ops kept un-fused to match XLA f32 math)
    float fi = (float)i - 63.5f;
    float fj = (float)j - 63.5f;
    float src_i = __fadd_rn(__fadd_rn(__fmul_rn(c, fi), __fmul_rn(s, fj)), 63.5f);
    float src_j = __fadd_rn(__fadd_rn(__fmul_rn(-s, fi), __fmul_rn(c, fj)), 63.5f);
    int si = __float2int_rn(src_i);   // round-half-to-even == jnp.round
    int sj = __float2int_rn(src_j);
    bool valid = (si >= 0) && (si < 128) && (sj >= 0) && (sj < 128);

    // flip D: out granule lane=(d*4+f4) reads src granule ((7-d)*4+f4)
    int d  = lane >> 2;
    int f4 = lane & 3;
    int srclane = ((7 - d) << 2) | f4;

    float4 v[ILP];
#pragma unroll
    for (int u = 0; u < ILP; u++)
        v[u] = make_float4(0.f, 0.f, 0.f, 0.f);

    if (valid) {
        // src float4 index for batch b0: ((b0*128+si)*128+sj)*32 + srclane
        size_t src0 = (((size_t)si * 128 + sj) * 32) + srclane
                    + (size_t)(chunk >> 14) * (128u * 128u * 32u);
        const size_t bstride = 4u * 128u * 128u * 32u;   // 4 batches of float4s
#pragma unroll
        for (int u = 0; u < ILP; u++)
            v[u] = __ldg(&in[src0 + (size_t)u * bstride]);
    }

    const size_t ostride = 4u * 128u * 128u * 32u;       // same stride on output
#pragma unroll
    for (int u = 0; u < ILP; u++)
        __stcs(&out[(size_t)tid + (size_t)u * ostride], v[u]);
}

extern "C" void kernel_launch(void* const* d_in, const int* in_sizes, int n_in,
                              void* d_out, int out_size)
{
    const float4* in  = (const float4*)d_in[0];
    float4*       out = (float4*)d_out;
    // total float4 = 8,388,608; each thread writes ILP=4
    int total_threads = (out_size / 4) / ILP;   // 2,097,152
    int threads = 256;
    int blocks = total_threads / threads;       // 8192
    Augment_70566312673947_kernel<<<blocks, threads>>>(in, out);
}

// round 4
// speedup vs baseline: 1.0528x; 1.0073x over previous
#include <cuda_runtime.h>
#include <cstdint>

// features: [B=16, H=128, W=128, D=8, F=16] float32, row-major.
// out[b,h,w,d,f] = valid(i,j) ? in[b, si(i,j), sj(i,j), 7-d, f] : 0
//   i = (h-5) mod 128, j = (134-w) mod 128
//   (si,sj) = round_ne( Rinv * (i-63.5, j-63.5) + 63.5 ), Rinv for +40 deg.
//
// One thread = one float4 lane within a 512B (d,f) chunk, for EIGHT batches
// (b0, b0+2, ..., b0+14). Rotation math computed once per thread; 8
// independent loads give MLP=8. Streaming stores keep input resident in L2.

#define ILP 8

__global__ __launch_bounds__(256) void Augment_70566312673947_kernel(
    const float4* __restrict__ in, float4* __restrict__ out)
{
    const float c = 0.76604443f;   // cos(40deg) rounded to f32
    const float s = 0.64278761f;   // sin(40deg) rounded to f32

    int tid = blockIdx.x * blockDim.x + threadIdx.x;   // 0 .. 1,048,575
    int lane  = tid & 31;          // float4 index within 512B chunk
    int chunk = tid >> 5;          // b0*H*W + h*W + w, b0 in [0,2)

    int w = chunk & 127;
    int h = (chunk >> 7) & 127;

    // roll^-1 then flip-W composed
    int i = h - 5; if (i < 0) i += 128;
    int j = (134 - w) & 127;

    // inverse rotation (f32 ops kept un-fused to match XLA f32 math)
    float fi = (float)i - 63.5f;
    float fj = (float)j - 63.5f;
    float src_i = __fadd_rn(__fadd_rn(__fmul_rn(c, fi), __fmul_rn(s, fj)), 63.5f);
    float src_j = __fadd_rn(__fadd_rn(__fmul_rn(-s, fi), __fmul_rn(c, fj)), 63.5f);
    int si = __float2int_rn(src_i);   // round-half-to-even == jnp.round
    int sj = __float2int_rn(src_j);
    bool valid = (si >= 0) && (si < 128) && (sj >= 0) && (sj < 128);

    // flip D: out granule lane=(d*4+f4) reads src granule ((7-d)*4+f4)
    int d  = lane >> 2;
    int f4 = lane & 3;
    int srclane = ((7 - d) << 2) | f4;

    // batch stride (2 batches apart) in float4 units
    const size_t bstride = 2u * 128u * 128u * 32u;   // 1,048,576

    float4 v[ILP];
#pragma unroll
    for (int u = 0; u < ILP; u++)
        v[u] = make_float4(0.f, 0.f, 0.f, 0.f);

    if (valid) {
        // src float4 index for batch b0: ((b0*128+si)*128+sj)*32 + srclane
        size_t src0 = (((size_t)si * 128 + sj) * 32) + srclane
                    + (size_t)(chunk >> 14) * (128u * 128u * 32u);
#pragma unroll
        for (int u = 0; u < ILP; u++)
            v[u] = __ldg(&in[src0 + (size_t)u * bstride]);
    }

#pragma unroll
    for (int u = 0; u < ILP; u++)
        __stcs(&out[(size_t)tid + (size_t)u * bstride], v[u]);
}

extern "C" void kernel_launch(void* const* d_in, const int* in_sizes, int n_in,
                              void* d_out, int out_size)
{
    const float4* in  = (const float4*)d_in[0];
    float4*       out = (float4*)d_out;
    // total float4 = 8,388,608; each thread writes ILP=8
    int total_threads = (out_size / 4) / ILP;   // 1,048,576
    int threads = 256;
    int blocks = total_threads / threads;       // 4096
    Augment_70566312673947_kernel<<<blocks, threads>>>(in, out);
}